// round 14
// baseline (speedup 1.0000x reference)
#include <cuda_runtime.h>
#include <cuda_bf16.h>
#include <cstdint>

#define NN 8192
#define FF 256
#define CHUNKS 256
#define LCH 32            // NN / CHUNKS
#define RANK_SEGS 4
#define RANK_TILE 2048    // NN / RANK_SEGS
#define QP (NN / 4)       // quarter-point prefix entries (8 per chunk)

#define BM 128
#define BN 128
#define BK 64
#define NSTAGE 3
#define GT 512                                    // GEMM threads (16 warps)
#define ASTR 72                                   // bf16 elems per smem row (64 + 8 pad)
#define STAGE_ELEMS ((BM + BN) * ASTR * 2)        // 36864 bf16 per stage (h+l)
#define SMEM_BYTES (NSTAGE * STAGE_ELEMS * 2)     // 221184 bytes

#define OUTR 16                                   // rows per k_out block

using bf16 = __nv_bfloat16;

// ---------------- scratch (device globals; no allocations allowed) ----------
__device__ float g_t[NN];
__device__ float g_c[NN];
__device__ float g_diag[NN];
__device__ unsigned g_key[NN];
__device__ int   g_rp[RANK_SEGS * NN];
__device__ float g_tsorted[NN];
__device__ int   g_perm[NN];
__device__ int   g_mi[NN];
__device__ float g_H[NN * FF];                 // H = G @ W5^T
__device__ float g_cs0[CHUNKS * FF];           // chunk sums -> exclusive bases
__device__ float g_cs1[CHUNKS * FF];
__device__ float g_u0[FF];
__device__ float g_u1[FF];
__device__ float g_P0q[QP * FF];               // LOCAL quarter-point partials
__device__ float g_P1q[QP * FF];
// bf16 split operands
__device__ bf16 g_xh[NN * FF];
__device__ bf16 g_xl[NN * FF];
__device__ bf16 g_Gh[NN * FF];
__device__ bf16 g_Gl[NN * FF];
__device__ bf16 g_W6h[FF * FF];
__device__ bf16 g_W6l[FF * FF];
__device__ bf16 g_W5h[FF * FF];
__device__ bf16 g_W5l[FF * FF];

__device__ __forceinline__ float leaky_f(float z) { return fmaxf(z, 0.1f * z); }

__device__ __forceinline__ unsigned pack2(float a, float b, unsigned& lo) {
    bf16 ha = __float2bfloat16(a);
    bf16 hb = __float2bfloat16(b);
    bf16 la = __float2bfloat16(a - __bfloat162float(ha));
    bf16 lb = __float2bfloat16(b - __bfloat162float(hb));
    lo = (unsigned)__bfloat16_as_ushort(la) | ((unsigned)__bfloat16_as_ushort(lb) << 16);
    return (unsigned)__bfloat16_as_ushort(ha) | ((unsigned)__bfloat16_as_ushort(hb) << 16);
}

// ---------------- kernel 1: s,t,c,diag,keys + x split + W splits -------------
__global__ __launch_bounds__(256) void k_st(const float* __restrict__ x,
                                            const float* __restrict__ W3,
                                            const float* __restrict__ b3,
                                            const float* __restrict__ W6,
                                            const float* __restrict__ W5,
                                            bf16* __restrict__ xh,
                                            bf16* __restrict__ xl)
{
    int tid = threadIdx.x;
    if (blockIdx.x >= NN / 8) {
        int idx = (blockIdx.x - NN / 8) * 256 + tid;     // 0 .. 2*FF*FF/4-1
        const int half = FF * FF / 4;
        const float* src = (idx < half) ? W6 : W5;
        bf16* dh = (idx < half) ? g_W6h : g_W5h;
        bf16* dl = (idx < half) ? g_W6l : g_W5l;
        int e = (idx < half) ? idx : idx - half;
        float4 v = ((const float4*)src)[e];
        unsigned l0, l1, h0 = pack2(v.x, v.y, l0), h1 = pack2(v.z, v.w, l1);
        __stcg(&((uint2*)dh)[e], make_uint2(h0, h1));
        __stcg(&((uint2*)dl)[e], make_uint2(l0, l1));
        return;
    }

    __shared__ float w[2 * FF];
    w[tid] = W3[tid];
    w[tid + 256] = W3[tid + 256];
    __syncthreads();

    int warp = tid >> 5;
    int lane = tid & 31;
    int i = blockIdx.x * 8 + warp;
    const float* xr = x + (size_t)i * FF + lane * 8;
    float4 v0 = *(const float4*)xr;
    float4 v1 = *(const float4*)(xr + 4);
    float vv[8] = {v0.x, v0.y, v0.z, v0.w, v1.x, v1.y, v1.z, v1.w};

    float as = 0.f, at = 0.f;
#pragma unroll
    for (int u = 0; u < 8; ++u) {
        as += vv[u] * w[lane * 8 + u];
        at += vv[u] * w[FF + lane * 8 + u];
    }
#pragma unroll
    for (int o = 16; o > 0; o >>= 1) {
        as += __shfl_down_sync(0xFFFFFFFFu, as, o);
        at += __shfl_down_sync(0xFFFFFFFFu, at, o);
    }

    unsigned hp[4], lp[4];
#pragma unroll
    for (int u = 0; u < 4; ++u) hp[u] = pack2(vv[2 * u], vv[2 * u + 1], lp[u]);
    size_t off = (size_t)i * FF + lane * 8;
    __stcg((uint4*)(xh + off), make_uint4(hp[0], hp[1], hp[2], hp[3]));
    __stcg((uint4*)(xl + off), make_uint4(lp[0], lp[1], lp[2], lp[3]));

    if (lane == 0) {
        float b = b3[0];
        g_t[i] = at;
        g_c[i] = as + b;
        g_diag[i] = leaky_f(as + at + b);
        unsigned u = __float_as_uint(at);
        u = (u & 0x80000000u) ? ~u : (u | 0x80000000u);
        g_key[i] = (u & 0xFFFFE000u) | (unsigned)i;   // 19-bit value + 13-bit idx
    }
}

// ---------------- counting-sort rank (32-bit keys) ---------------------------
__global__ __launch_bounds__(256) void k_rankp()
{
    __shared__ unsigned tile[RANK_TILE];
    int j = blockIdx.x * 256 + threadIdx.x;
    unsigned kj = g_key[j];
    int base = blockIdx.y * RANK_TILE;
    for (int m = threadIdx.x; m < RANK_TILE; m += 256) tile[m] = g_key[base + m];
    __syncthreads();
    int cnt = 0;
#pragma unroll 32
    for (int m = 0; m < RANK_TILE; ++m) cnt += (tile[m] < kj) ? 1 : 0;
    g_rp[blockIdx.y * NN + j] = cnt;
}

__global__ __launch_bounds__(256) void k_scatter()
{
    int j = blockIdx.x * 256 + threadIdx.x;
    int rank = g_rp[j] + g_rp[NN + j] + g_rp[2 * NN + j] + g_rp[3 * NN + j];
    g_tsorted[rank] = g_t[j];
    g_perm[rank] = j;
}

// ---------------- binary search directly on global ---------------------------
__global__ __launch_bounds__(256) void k_search()
{
    int i = blockIdx.x * 256 + threadIdx.x;
    float keyv = -g_c[i];
    int lo = 0;
#pragma unroll
    for (int step = NN / 2; step > 0; step >>= 1) {
        int nxt = lo + step;
        if (__ldg(&g_tsorted[nxt - 1]) < keyv) lo = nxt;
    }
    g_mi[i] = lo;
}

// ---------------- tensor-core GEMM (split bf16, 3 terms, ldmatrix) -----------
__device__ __forceinline__ void mma16816(float c[4], const unsigned a[4], const unsigned b0, const unsigned b1)
{
    asm volatile(
        "mma.sync.aligned.m16n8k16.row.col.f32.bf16.bf16.f32 "
        "{%0,%1,%2,%3}, {%4,%5,%6,%7}, {%8,%9}, {%0,%1,%2,%3};\n"
        : "+f"(c[0]), "+f"(c[1]), "+f"(c[2]), "+f"(c[3])
        : "r"(a[0]), "r"(a[1]), "r"(a[2]), "r"(a[3]), "r"(b0), "r"(b1));
}

__device__ __forceinline__ void ldsm_x4(unsigned r[4], const bf16* p)
{
    unsigned a = (unsigned)__cvta_generic_to_shared(p);
    asm volatile("ldmatrix.sync.aligned.m8n8.x4.shared.b16 {%0,%1,%2,%3}, [%4];\n"
                 : "=r"(r[0]), "=r"(r[1]), "=r"(r[2]), "=r"(r[3]) : "r"(a));
}

#define CPA(dst, src) asm volatile("cp.async.cg.shared.global [%0], [%1], 16;\n" \
    :: "r"((unsigned)__cvta_generic_to_shared(dst)), "l"(src))

// 512 threads, 16 warps in 4x4 grid; each warp owns 32 rows x 32 cols.
// Single-sync multistage: the top barrier of iteration `it` guarantees all
// warps finished compute(it-1), which is the only reader of the buffer that
// load_stage(it+2) overwrites ((it+2)%3 == (it-1)%3).
// MODE 0: C = leaky(acc + bias) -> bf16 split (Ch, Cl)
// MODE 1: C = acc               -> fp32 (Cf)
template <int MODE>
__global__ __launch_bounds__(GT) void k_gemm_t(
    const bf16* __restrict__ Agh, const bf16* __restrict__ Agl,
    const bf16* __restrict__ Bgh, const bf16* __restrict__ Bgl,
    const float* __restrict__ bias,
    bf16* __restrict__ Ch, bf16* __restrict__ Cl, float* __restrict__ Cf)
{
    extern __shared__ bf16 sm[];
    const int tid = threadIdx.x;
    const int bm = blockIdx.x * BM;
    const int bn = blockIdx.y * BN;
    const int lane = tid & 31;
    const int warp = tid >> 5;        // 0..15
    const int wm = warp & 3;          // 4 m-tiles of 32
    const int wn = warp >> 2;         // 4 n-tiles of 32
    const int qr = lane >> 2;
    const int qc = (lane & 3) * 2;

    const int aoff = (lane & 15) * ASTR + ((lane >> 4) << 3);
    const int boff = ((lane & 7) + ((lane >> 4) << 3)) * ASTR + (((lane >> 3) & 1) << 3);

    float acc[2][4][4] = {};

    auto load_stage = [&](int kt, int buf) {
        bf16* Ah = sm + buf * STAGE_ELEMS;
        bf16* Al = Ah + BM * ASTR;
        bf16* Bh = Al + BM * ASTR;
        bf16* Bl = Bh + BN * ASTR;
#pragma unroll
        for (int l = 0; l < 2; ++l) {
            int e = tid + l * GT;              // 0..1023
            int row = e >> 3;                  // 0..127
            int seg = (e & 7) << 3;            // 0..56 (x8 elems = 16B)
            size_t ao = (size_t)(bm + row) * FF + kt + seg;
            CPA(Ah + row * ASTR + seg, Agh + ao);
            CPA(Al + row * ASTR + seg, Agl + ao);
            size_t bo = (size_t)(bn + row) * FF + kt + seg;
            CPA(Bh + row * ASTR + seg, Bgh + bo);
            CPA(Bl + row * ASTR + seg, Bgl + bo);
        }
        asm volatile("cp.async.commit_group;\n" ::);
    };

    load_stage(0, 0);
    load_stage(BK, 1);

    const int NIT = FF / BK;   // 4
    for (int it = 0; it < NIT; ++it) {
        if (it < NIT - 1) asm volatile("cp.async.wait_group 1;\n" ::);
        else              asm volatile("cp.async.wait_group 0;\n" ::);
        __syncthreads();
        if (it + 2 < NIT) load_stage((it + 2) * BK, (it + 2) % NSTAGE);

        int buf = it % NSTAGE;
        const bf16* Ah = sm + buf * STAGE_ELEMS;
        const bf16* Al = Ah + BM * ASTR;
        const bf16* Bh = Al + BM * ASTR;
        const bf16* Bl = Bh + BN * ASTR;

#pragma unroll
        for (int ks = 0; ks < BK; ks += 16) {
            unsigned ah[2][4], al[2][4];
#pragma unroll
            for (int mi = 0; mi < 2; mi++) {
                int rb = (wm * 32 + mi * 16) * ASTR + ks;
                ldsm_x4(ah[mi], Ah + rb + aoff);
                ldsm_x4(al[mi], Al + rb + aoff);
            }
            unsigned bhf[2][4], blf[2][4];
#pragma unroll
            for (int p = 0; p < 2; p++) {
                int nb = (wn * 32 + p * 16) * ASTR + ks;
                ldsm_x4(bhf[p], Bh + nb + boff);
                ldsm_x4(blf[p], Bl + nb + boff);
            }
#pragma unroll
            for (int ni = 0; ni < 4; ni++) {
                unsigned bh0 = bhf[ni >> 1][(ni & 1) * 2], bh1 = bhf[ni >> 1][(ni & 1) * 2 + 1];
                unsigned bl0 = blf[ni >> 1][(ni & 1) * 2], bl1 = blf[ni >> 1][(ni & 1) * 2 + 1];
#pragma unroll
                for (int mi = 0; mi < 2; mi++) {
                    mma16816(acc[mi][ni], ah[mi], bh0, bh1);
                    mma16816(acc[mi][ni], ah[mi], bl0, bl1);
                    mma16816(acc[mi][ni], al[mi], bh0, bh1);
                }
            }
        }
        // no bottom barrier: top barrier of next iteration provides the
        // write-after-read protection for the 3-stage ring (see comment above)
    }

#pragma unroll
    for (int mi = 0; mi < 2; mi++) {
        int r = bm + wm * 32 + mi * 16 + qr;
#pragma unroll
        for (int ni = 0; ni < 4; ni++) {
            int cl = bn + wn * 32 + ni * 8 + qc;
            size_t o0 = (size_t)r * FF + cl;
            size_t o8 = (size_t)(r + 8) * FF + cl;
            if (MODE == 0) {
                float b0 = bias[cl], b1 = bias[cl + 1];
                float v0 = leaky_f(acc[mi][ni][0] + b0);
                float v1 = leaky_f(acc[mi][ni][1] + b1);
                float v2 = leaky_f(acc[mi][ni][2] + b0);
                float v3 = leaky_f(acc[mi][ni][3] + b1);
                unsigned l01, l23;
                unsigned h01 = pack2(v0, v1, l01);
                unsigned h23 = pack2(v2, v3, l23);
                __stcg((unsigned*)(Ch + o0), h01);
                __stcg((unsigned*)(Cl + o0), l01);
                __stcg((unsigned*)(Ch + o8), h23);
                __stcg((unsigned*)(Cl + o8), l23);
            } else {
                __stcg((float2*)(Cf + o0), make_float2(acc[mi][ni][0], acc[mi][ni][1]));
                __stcg((float2*)(Cf + o8), make_float2(acc[mi][ni][2], acc[mi][ni][3]));
            }
        }
    }
}

// ---- chunk sums + LOCAL quarter partials (no scan here) ---------------------
__global__ __launch_bounds__(256) void k_csum()
{
    __shared__ int spj[LCH];
    __shared__ float spt[LCH];
    int c = blockIdx.x;
    int k = threadIdx.x;
    if (k < LCH) {
        spj[k] = g_perm[c * LCH + k];
        spt[k] = g_tsorted[c * LCH + k];
    }
    __syncthreads();
    float a0 = 0.f, a1 = 0.f;
#pragma unroll
    for (int r = 0; r < LCH; ++r) {
        if ((r & 3) == 0) {
            size_t off = (size_t)(c * 8 + (r >> 2)) * FF + k;
            __stcg(&g_P0q[off], a0);  // local partial before row r of this chunk
            __stcg(&g_P1q[off], a1);
        }
        float h = g_H[(size_t)spj[r] * FF + k];
        a0 += h;
        a1 += spt[r] * h;
    }
    g_cs0[c * FF + k] = a0;
    g_cs1[c * FF + k] = a1;
}

// ---- parallel scan over chunks: one block per column -------------------------
__global__ __launch_bounds__(CHUNKS) void k_scan2()
{
    __shared__ float s0[CHUNKS], s1[CHUNKS];
    int k = blockIdx.x;            // column 0..FF-1
    int t = threadIdx.x;           // chunk 0..CHUNKS-1
    float v0 = g_cs0[t * FF + k];
    float v1 = g_cs1[t * FF + k];
    float a0 = v0, a1 = v1;
    s0[t] = a0; s1[t] = a1;
    __syncthreads();
#pragma unroll
    for (int d = 1; d < CHUNKS; d <<= 1) {
        float b0 = (t >= d) ? s0[t - d] : 0.f;
        float b1 = (t >= d) ? s1[t - d] : 0.f;
        __syncthreads();
        a0 += b0; a1 += b1;
        s0[t] = a0; s1[t] = a1;
        __syncthreads();
    }
    g_cs0[t * FF + k] = a0 - v0;   // exclusive chunk base
    g_cs1[t * FF + k] = a1 - v1;
    if (t == CHUNKS - 1) { g_u0[k] = a0; g_u1[k] = a1; }
}

// ---------------- output epilogue ---------------------------------------------
__global__ __launch_bounds__(256) void k_out(const float* __restrict__ x,
                                             const float* __restrict__ b5,
                                             float* __restrict__ out)
{
    __shared__ int smi[OUTR];
    __shared__ float sci[OUTR], sdi[OUTR];
    int k = threadIdx.x;
    if (k < OUTR) {
        int i = blockIdx.x * OUTR + k;
        smi[k] = g_mi[i];
        sci[k] = g_c[i];
        sdi[k] = g_diag[i];
    }
    __syncthreads();
    float u0 = g_u0[k];
    float u1 = g_u1[k];
    float bk = b5[k];
    const float inv = 1.0f / (float)(NN - 1);
#pragma unroll 4
    for (int r = 0; r < OUTR; ++r) {
        int i = blockIdx.x * OUTR + r;
        int m = smi[r];
        float ci = sci[r], di = sdi[r];
        int q = (m + 2) >> 2;          // nearest quarter point
        if (q > QP) q = QP;
        float p0, p1;
        if (q < QP) {
            int c2 = q >> 3;           // owning chunk
            p0 = g_cs0[(size_t)c2 * FF + k] + g_P0q[(size_t)q * FF + k];
            p1 = g_cs1[(size_t)c2 * FF + k] + g_P1q[(size_t)q * FF + k];
        } else {
            p0 = u0;
            p1 = u1;
        }
        int qm = q << 2;
        if (qm <= m) {
            for (int rr = qm; rr < m; ++rr) {
                int j = __ldg(&g_perm[rr]);
                float tv = __ldg(&g_tsorted[rr]);
                float h = g_H[(size_t)j * FF + k];
                p0 += h;
                p1 += tv * h;
            }
        } else {
            for (int rr = m; rr < qm; ++rr) {
                int j = __ldg(&g_perm[rr]);
                float tv = __ldg(&g_tsorted[rr]);
                float h = g_H[(size_t)j * FF + k];
                p0 -= h;
                p1 -= tv * h;
            }
        }
        float h = g_H[(size_t)i * FF + k];
        float val = (ci * u0 + u1 - 0.9f * (ci * p0 + p1) - di * h) * inv;
        out[(size_t)i * FF + k] = leaky_f(val + bk) + x[(size_t)i * FF + k];
    }
}

// ---------------- launch -----------------------------------------------------
extern "C" void kernel_launch(void* const* d_in, const int* in_sizes, int n_in,
                              void* d_out, int out_size)
{
    const float* x  = (const float*)d_in[0];
    const float* W3 = (const float*)d_in[1];
    const float* b3 = (const float*)d_in[2];
    const float* W6 = (const float*)d_in[3];
    const float* b6 = (const float*)d_in[4];
    const float* W5 = (const float*)d_in[5];
    const float* b5 = (const float*)d_in[6];
    float* out = (float*)d_out;

    void *pH, *pxh, *pxl, *pGh, *pGl, *pW6h, *pW6l, *pW5h, *pW5l;
    cudaGetSymbolAddress(&pH, g_H);
    cudaGetSymbolAddress(&pxh, g_xh);
    cudaGetSymbolAddress(&pxl, g_xl);
    cudaGetSymbolAddress(&pGh, g_Gh);
    cudaGetSymbolAddress(&pGl, g_Gl);
    cudaGetSymbolAddress(&pW6h, g_W6h);
    cudaGetSymbolAddress(&pW6l, g_W6l);
    cudaGetSymbolAddress(&pW5h, g_W5h);
    cudaGetSymbolAddress(&pW5l, g_W5l);

    cudaFuncSetAttribute(k_gemm_t<0>, cudaFuncAttributeMaxDynamicSharedMemorySize, SMEM_BYTES);
    cudaFuncSetAttribute(k_gemm_t<1>, cudaFuncAttributeMaxDynamicSharedMemorySize, SMEM_BYTES);

    dim3 ggrid(NN / BM, FF / BN);

    k_st<<<NN / 8 + 128, 256>>>(x, W3, b3, W6, W5, (bf16*)pxh, (bf16*)pxl);

    // fork: sort chain on side stream, GEMMs on main stream
    cudaStream_t s1 = 0;
    cudaEvent_t e0 = 0, e1 = 0;
    bool forked = false;
    if (cudaStreamCreateWithFlags(&s1, cudaStreamNonBlocking) == cudaSuccess) {
        if (cudaEventCreateWithFlags(&e0, cudaEventDisableTiming) == cudaSuccess &&
            cudaEventCreateWithFlags(&e1, cudaEventDisableTiming) == cudaSuccess) {
            forked = true;
        }
    }

    if (forked) {
        cudaEventRecord(e0, 0);
        cudaStreamWaitEvent(s1, e0, 0);
        k_rankp<<<dim3(NN / 256, RANK_SEGS), 256, 0, s1>>>();
        k_scatter<<<NN / 256, 256, 0, s1>>>();
        k_search<<<NN / 256, 256, 0, s1>>>();
        cudaEventRecord(e1, s1);
    } else {
        k_rankp<<<dim3(NN / 256, RANK_SEGS), 256>>>();
        k_scatter<<<NN / 256, 256>>>();
        k_search<<<NN / 256, 256>>>();
    }

    k_gemm_t<0><<<ggrid, GT, SMEM_BYTES>>>((const bf16*)pxh, (const bf16*)pxl,
                                           (const bf16*)pW6h, (const bf16*)pW6l,
                                           b6, (bf16*)pGh, (bf16*)pGl, nullptr);
    k_gemm_t<1><<<ggrid, GT, SMEM_BYTES>>>((const bf16*)pGh, (const bf16*)pGl,
                                           (const bf16*)pW5h, (const bf16*)pW5l,
                                           nullptr, nullptr, nullptr, (float*)pH);

    if (forked) {
        cudaStreamWaitEvent(0, e1, 0);   // join before csum (needs perm/tsorted/mi)
    }

    k_csum<<<CHUNKS, 256>>>();
    k_scan2<<<FF, CHUNKS>>>();
    k_out<<<NN / OUTR, 256>>>(x, b5, out);
}

// round 15
// speedup vs baseline: 1.0799x; 1.0799x over previous
#include <cuda_runtime.h>
#include <cuda_bf16.h>
#include <cstdint>

#define NN 8192
#define FF 256
#define CHUNKS 256
#define LCH 32            // NN / CHUNKS
#define RANK_SEGS 4
#define RANK_TILE 2048    // NN / RANK_SEGS
#define QP (NN / 4)       // quarter-point prefix entries (8 per chunk)

#define BM 128
#define BN 128
#define BK 64
#define NSTAGE 3
#define GT 512                                    // GEMM threads (16 warps)
#define ASTR 72                                   // bf16 elems per smem row (64 + 8 pad)
#define STAGE_ELEMS ((BM + BN) * ASTR * 2)        // 36864 bf16 per stage (h+l)
#define SMEM_BYTES (NSTAGE * STAGE_ELEMS * 2)     // 221184 bytes

using bf16 = __nv_bfloat16;

// ---------------- scratch (device globals; no allocations allowed) ----------
__device__ float g_t[NN];
__device__ float g_c[NN];
__device__ float g_diag[NN];
__device__ unsigned g_key[NN];
__device__ int   g_rp[RANK_SEGS * NN];
__device__ float g_tsorted[NN];
__device__ int   g_perm[NN];
__device__ int   g_mi[NN];
__device__ float g_H[NN * FF];                 // H = G @ W5^T
__device__ float g_cs0[CHUNKS * FF];           // chunk sums -> exclusive bases
__device__ float g_cs1[CHUNKS * FF];
__device__ float g_u0[FF];
__device__ float g_u1[FF];
__device__ float g_P0q[QP * FF];               // LOCAL quarter-point partials
__device__ float g_P1q[QP * FF];
// bf16 split operands
__device__ bf16 g_xh[NN * FF];
__device__ bf16 g_xl[NN * FF];
__device__ bf16 g_Gh[NN * FF];
__device__ bf16 g_Gl[NN * FF];
__device__ bf16 g_W6h[FF * FF];
__device__ bf16 g_W6l[FF * FF];
__device__ bf16 g_W5h[FF * FF];
__device__ bf16 g_W5l[FF * FF];

__device__ __forceinline__ float leaky_f(float z) { return fmaxf(z, 0.1f * z); }

__device__ __forceinline__ unsigned pack2(float a, float b, unsigned& lo) {
    bf16 ha = __float2bfloat16(a);
    bf16 hb = __float2bfloat16(b);
    bf16 la = __float2bfloat16(a - __bfloat162float(ha));
    bf16 lb = __float2bfloat16(b - __bfloat162float(hb));
    lo = (unsigned)__bfloat16_as_ushort(la) | ((unsigned)__bfloat16_as_ushort(lb) << 16);
    return (unsigned)__bfloat16_as_ushort(ha) | ((unsigned)__bfloat16_as_ushort(hb) << 16);
}

// ---------------- kernel 1: W splits (first 128 blocks) + s,t,c,diag,keys + x split
__global__ __launch_bounds__(256) void k_st(const float* __restrict__ x,
                                            const float* __restrict__ W3,
                                            const float* __restrict__ b3,
                                            const float* __restrict__ W6,
                                            const float* __restrict__ W5,
                                            bf16* __restrict__ xh,
                                            bf16* __restrict__ xl)
{
    int tid = threadIdx.x;
    if (blockIdx.x < 128) {
        // weight-conversion blocks scheduled first so W splits land earliest
        int idx = blockIdx.x * 256 + tid;                // 0 .. 2*FF*FF/4-1
        const int half = FF * FF / 4;
        const float* src = (idx < half) ? W6 : W5;
        bf16* dh = (idx < half) ? g_W6h : g_W5h;
        bf16* dl = (idx < half) ? g_W6l : g_W5l;
        int e = (idx < half) ? idx : idx - half;
        float4 v = ((const float4*)src)[e];
        unsigned l0, l1, h0 = pack2(v.x, v.y, l0), h1 = pack2(v.z, v.w, l1);
        ((uint2*)dh)[e] = make_uint2(h0, h1);
        ((uint2*)dl)[e] = make_uint2(l0, l1);
        return;
    }

    __shared__ float w[2 * FF];
    w[tid] = W3[tid];
    w[tid + 256] = W3[tid + 256];
    __syncthreads();

    int warp = tid >> 5;
    int lane = tid & 31;
    int i = (blockIdx.x - 128) * 8 + warp;
    const float* xr = x + (size_t)i * FF + lane * 8;
    float4 v0 = *(const float4*)xr;
    float4 v1 = *(const float4*)(xr + 4);
    float vv[8] = {v0.x, v0.y, v0.z, v0.w, v1.x, v1.y, v1.z, v1.w};

    float as = 0.f, at = 0.f;
#pragma unroll
    for (int u = 0; u < 8; ++u) {
        as += vv[u] * w[lane * 8 + u];
        at += vv[u] * w[FF + lane * 8 + u];
    }
#pragma unroll
    for (int o = 16; o > 0; o >>= 1) {
        as += __shfl_down_sync(0xFFFFFFFFu, as, o);
        at += __shfl_down_sync(0xFFFFFFFFu, at, o);
    }

    unsigned hp[4], lp[4];
#pragma unroll
    for (int u = 0; u < 4; ++u) hp[u] = pack2(vv[2 * u], vv[2 * u + 1], lp[u]);
    size_t off = (size_t)i * FF + lane * 8;
    *(uint4*)(xh + off) = make_uint4(hp[0], hp[1], hp[2], hp[3]);
    *(uint4*)(xl + off) = make_uint4(lp[0], lp[1], lp[2], lp[3]);

    if (lane == 0) {
        float b = b3[0];
        g_t[i] = at;
        g_c[i] = as + b;
        g_diag[i] = leaky_f(as + at + b);
        unsigned u = __float_as_uint(at);
        u = (u & 0x80000000u) ? ~u : (u | 0x80000000u);
        g_key[i] = (u & 0xFFFFE000u) | (unsigned)i;   // 19-bit value + 13-bit idx
    }
}

// ---------------- counting-sort rank (32-bit keys) ---------------------------
__global__ __launch_bounds__(256) void k_rankp()
{
    __shared__ unsigned tile[RANK_TILE];
    int j = blockIdx.x * 256 + threadIdx.x;
    unsigned kj = g_key[j];
    int base = blockIdx.y * RANK_TILE;
    for (int m = threadIdx.x; m < RANK_TILE; m += 256) tile[m] = g_key[base + m];
    __syncthreads();
    int cnt = 0;
#pragma unroll 32
    for (int m = 0; m < RANK_TILE; ++m) cnt += (tile[m] < kj) ? 1 : 0;
    g_rp[blockIdx.y * NN + j] = cnt;
}

__global__ __launch_bounds__(256) void k_scatter()
{
    int j = blockIdx.x * 256 + threadIdx.x;
    int rank = g_rp[j] + g_rp[NN + j] + g_rp[2 * NN + j] + g_rp[3 * NN + j];
    g_tsorted[rank] = g_t[j];
    g_perm[rank] = j;
}

// ---------------- binary search directly on global ---------------------------
__global__ __launch_bounds__(256) void k_search()
{
    int i = blockIdx.x * 256 + threadIdx.x;
    float keyv = -g_c[i];
    int lo = 0;
#pragma unroll
    for (int step = NN / 2; step > 0; step >>= 1) {
        int nxt = lo + step;
        if (__ldg(&g_tsorted[nxt - 1]) < keyv) lo = nxt;
    }
    g_mi[i] = lo;
}

// ---------------- tensor-core GEMM (split bf16, 3 terms, ldmatrix) -----------
__device__ __forceinline__ void mma16816(float c[4], const unsigned a[4], const unsigned b0, const unsigned b1)
{
    asm volatile(
        "mma.sync.aligned.m16n8k16.row.col.f32.bf16.bf16.f32 "
        "{%0,%1,%2,%3}, {%4,%5,%6,%7}, {%8,%9}, {%0,%1,%2,%3};\n"
        : "+f"(c[0]), "+f"(c[1]), "+f"(c[2]), "+f"(c[3])
        : "r"(a[0]), "r"(a[1]), "r"(a[2]), "r"(a[3]), "r"(b0), "r"(b1));
}

__device__ __forceinline__ void ldsm_x4(unsigned r[4], const bf16* p)
{
    unsigned a = (unsigned)__cvta_generic_to_shared(p);
    asm volatile("ldmatrix.sync.aligned.m8n8.x4.shared.b16 {%0,%1,%2,%3}, [%4];\n"
                 : "=r"(r[0]), "=r"(r[1]), "=r"(r[2]), "=r"(r[3]) : "r"(a));
}

#define CPA(dst, src) asm volatile("cp.async.cg.shared.global [%0], [%1], 16;\n" \
    :: "r"((unsigned)__cvta_generic_to_shared(dst)), "l"(src))

// 512 threads, 16 warps in 4x4 grid; each warp owns 32 rows x 32 cols.
// MODE 0: C = leaky(acc + bias) -> bf16 split (Ch, Cl)
// MODE 1: C = acc               -> fp32 (Cf)
template <int MODE>
__global__ __launch_bounds__(GT) void k_gemm_t(
    const bf16* __restrict__ Agh, const bf16* __restrict__ Agl,
    const bf16* __restrict__ Bgh, const bf16* __restrict__ Bgl,
    const float* __restrict__ bias,
    bf16* __restrict__ Ch, bf16* __restrict__ Cl, float* __restrict__ Cf)
{
    extern __shared__ bf16 sm[];
    const int tid = threadIdx.x;
    const int bm = blockIdx.x * BM;
    const int bn = blockIdx.y * BN;
    const int lane = tid & 31;
    const int warp = tid >> 5;        // 0..15
    const int wm = warp & 3;          // 4 m-tiles of 32
    const int wn = warp >> 2;         // 4 n-tiles of 32
    const int qr = lane >> 2;
    const int qc = (lane & 3) * 2;

    const int aoff = (lane & 15) * ASTR + ((lane >> 4) << 3);
    const int boff = ((lane & 7) + ((lane >> 4) << 3)) * ASTR + (((lane >> 3) & 1) << 3);

    float acc[2][4][4] = {};

    auto load_stage = [&](int kt, int buf) {
        bf16* Ah = sm + buf * STAGE_ELEMS;
        bf16* Al = Ah + BM * ASTR;
        bf16* Bh = Al + BM * ASTR;
        bf16* Bl = Bh + BN * ASTR;
#pragma unroll
        for (int l = 0; l < 2; ++l) {
            int e = tid + l * GT;              // 0..1023
            int row = e >> 3;                  // 0..127
            int seg = (e & 7) << 3;            // 0..56 (x8 elems = 16B)
            size_t ao = (size_t)(bm + row) * FF + kt + seg;
            CPA(Ah + row * ASTR + seg, Agh + ao);
            CPA(Al + row * ASTR + seg, Agl + ao);
            size_t bo = (size_t)(bn + row) * FF + kt + seg;
            CPA(Bh + row * ASTR + seg, Bgh + bo);
            CPA(Bl + row * ASTR + seg, Bgl + bo);
        }
        asm volatile("cp.async.commit_group;\n" ::);
    };

    load_stage(0, 0);
    load_stage(BK, 1);

    const int NIT = FF / BK;   // 4
    for (int it = 0; it < NIT; ++it) {
        // prefetch issued BEFORE the wait: buffer (it+2)%3 == (it-1)%3 was
        // fully consumed before the bottom barrier of iteration it-1, which
        // all threads passed; cp.async issue does not depend on wait_group.
        if (it + 2 < NIT) load_stage((it + 2) * BK, (it + 2) % NSTAGE);
        if (it < NIT - 1) asm volatile("cp.async.wait_group 1;\n" ::);
        else              asm volatile("cp.async.wait_group 0;\n" ::);
        __syncthreads();

        int buf = it % NSTAGE;
        const bf16* Ah = sm + buf * STAGE_ELEMS;
        const bf16* Al = Ah + BM * ASTR;
        const bf16* Bh = Al + BM * ASTR;
        const bf16* Bl = Bh + BN * ASTR;

#pragma unroll
        for (int ks = 0; ks < BK; ks += 16) {
            unsigned ah[2][4], al[2][4];
#pragma unroll
            for (int mi = 0; mi < 2; mi++) {
                int rb = (wm * 32 + mi * 16) * ASTR + ks;
                ldsm_x4(ah[mi], Ah + rb + aoff);
                ldsm_x4(al[mi], Al + rb + aoff);
            }
            unsigned bhf[2][4], blf[2][4];
#pragma unroll
            for (int p = 0; p < 2; p++) {
                int nb = (wn * 32 + p * 16) * ASTR + ks;
                ldsm_x4(bhf[p], Bh + nb + boff);
                ldsm_x4(blf[p], Bl + nb + boff);
            }
#pragma unroll
            for (int ni = 0; ni < 4; ni++) {
                unsigned bh0 = bhf[ni >> 1][(ni & 1) * 2], bh1 = bhf[ni >> 1][(ni & 1) * 2 + 1];
                unsigned bl0 = blf[ni >> 1][(ni & 1) * 2], bl1 = blf[ni >> 1][(ni & 1) * 2 + 1];
#pragma unroll
                for (int mi = 0; mi < 2; mi++) {
                    mma16816(acc[mi][ni], ah[mi], bh0, bh1);
                    mma16816(acc[mi][ni], ah[mi], bl0, bl1);
                    mma16816(acc[mi][ni], al[mi], bh0, bh1);
                }
            }
        }
        __syncthreads();
    }

#pragma unroll
    for (int mi = 0; mi < 2; mi++) {
        int r = bm + wm * 32 + mi * 16 + qr;
#pragma unroll
        for (int ni = 0; ni < 4; ni++) {
            int cl = bn + wn * 32 + ni * 8 + qc;
            size_t o0 = (size_t)r * FF + cl;
            size_t o8 = (size_t)(r + 8) * FF + cl;
            if (MODE == 0) {
                float b0 = bias[cl], b1 = bias[cl + 1];
                float v0 = leaky_f(acc[mi][ni][0] + b0);
                float v1 = leaky_f(acc[mi][ni][1] + b1);
                float v2 = leaky_f(acc[mi][ni][2] + b0);
                float v3 = leaky_f(acc[mi][ni][3] + b1);
                unsigned l01, l23;
                unsigned h01 = pack2(v0, v1, l01);
                unsigned h23 = pack2(v2, v3, l23);
                *(unsigned*)(Ch + o0) = h01;
                *(unsigned*)(Cl + o0) = l01;
                *(unsigned*)(Ch + o8) = h23;
                *(unsigned*)(Cl + o8) = l23;
            } else {
                *(float2*)(Cf + o0) = make_float2(acc[mi][ni][0], acc[mi][ni][1]);
                *(float2*)(Cf + o8) = make_float2(acc[mi][ni][2], acc[mi][ni][3]);
            }
        }
    }
}

// ---- chunk sums + LOCAL quarter partials (no scan here) ---------------------
__global__ __launch_bounds__(256) void k_csum()
{
    __shared__ int spj[LCH];
    __shared__ float spt[LCH];
    int c = blockIdx.x;
    int k = threadIdx.x;
    if (k < LCH) {
        spj[k] = g_perm[c * LCH + k];
        spt[k] = g_tsorted[c * LCH + k];
    }
    __syncthreads();
    float a0 = 0.f, a1 = 0.f;
#pragma unroll
    for (int r = 0; r < LCH; ++r) {
        if ((r & 3) == 0) {
            size_t off = (size_t)(c * 8 + (r >> 2)) * FF + k;
            g_P0q[off] = a0;          // local partial before row r of this chunk
            g_P1q[off] = a1;
        }
        float h = g_H[(size_t)spj[r] * FF + k];
        a0 += h;
        a1 += spt[r] * h;
    }
    g_cs0[c * FF + k] = a0;
    g_cs1[c * FF + k] = a1;
}

// ---- parallel scan over chunks: one block per column -------------------------
__global__ __launch_bounds__(CHUNKS) void k_scan2()
{
    __shared__ float s0[CHUNKS], s1[CHUNKS];
    int k = blockIdx.x;            // column 0..FF-1
    int t = threadIdx.x;           // chunk 0..CHUNKS-1
    float v0 = g_cs0[t * FF + k];
    float v1 = g_cs1[t * FF + k];
    float a0 = v0, a1 = v1;
    s0[t] = a0; s1[t] = a1;
    __syncthreads();
#pragma unroll
    for (int d = 1; d < CHUNKS; d <<= 1) {
        float b0 = (t >= d) ? s0[t - d] : 0.f;
        float b1 = (t >= d) ? s1[t - d] : 0.f;
        __syncthreads();
        a0 += b0; a1 += b1;
        s0[t] = a0; s1[t] = a1;
        __syncthreads();
    }
    g_cs0[t * FF + k] = a0 - v0;   // exclusive chunk base
    g_cs1[t * FF + k] = a1 - v1;
    if (t == CHUNKS - 1) { g_u0[k] = a0; g_u1[k] = a1; }
}

// ---------------- output epilogue ---------------------------------------------
__global__ __launch_bounds__(256) void k_out(const float* __restrict__ x,
                                             const float* __restrict__ b5,
                                             float* __restrict__ out)
{
    __shared__ int smi8[8];
    __shared__ float sc8[8], sd8[8];
    int k = threadIdx.x;
    if (k < 8) {
        int i = blockIdx.x * 8 + k;
        smi8[k] = g_mi[i];
        sc8[k] = g_c[i];
        sd8[k] = g_diag[i];
    }
    __syncthreads();
    float u0 = g_u0[k];
    float u1 = g_u1[k];
    float bk = b5[k];
    const float inv = 1.0f / (float)(NN - 1);
#pragma unroll
    for (int r = 0; r < 8; ++r) {
        int i = blockIdx.x * 8 + r;
        int m = smi8[r];
        float ci = sc8[r], di = sd8[r];
        int q = (m + 2) >> 2;          // nearest quarter point
        if (q > QP) q = QP;
        float p0, p1;
        if (q < QP) {
            int c2 = q >> 3;           // owning chunk
            p0 = g_cs0[(size_t)c2 * FF + k] + g_P0q[(size_t)q * FF + k];
            p1 = g_cs1[(size_t)c2 * FF + k] + g_P1q[(size_t)q * FF + k];
        } else {
            p0 = u0;
            p1 = u1;
        }
        int qm = q << 2;
        if (qm <= m) {
            for (int rr = qm; rr < m; ++rr) {
                int j = __ldg(&g_perm[rr]);
                float tv = __ldg(&g_tsorted[rr]);
                float h = g_H[(size_t)j * FF + k];
                p0 += h;
                p1 += tv * h;
            }
        } else {
            for (int rr = m; rr < qm; ++rr) {
                int j = __ldg(&g_perm[rr]);
                float tv = __ldg(&g_tsorted[rr]);
                float h = g_H[(size_t)j * FF + k];
                p0 -= h;
                p1 -= tv * h;
            }
        }
        float h = g_H[(size_t)i * FF + k];
        float val = (ci * u0 + u1 - 0.9f * (ci * p0 + p1) - di * h) * inv;
        out[(size_t)i * FF + k] = leaky_f(val + bk) + x[(size_t)i * FF + k];
    }
}

// ---------------- launch -----------------------------------------------------
extern "C" void kernel_launch(void* const* d_in, const int* in_sizes, int n_in,
                              void* d_out, int out_size)
{
    const float* x  = (const float*)d_in[0];
    const float* W3 = (const float*)d_in[1];
    const float* b3 = (const float*)d_in[2];
    const float* W6 = (const float*)d_in[3];
    const float* b6 = (const float*)d_in[4];
    const float* W5 = (const float*)d_in[5];
    const float* b5 = (const float*)d_in[6];
    float* out = (float*)d_out;

    void *pH, *pxh, *pxl, *pGh, *pGl, *pW6h, *pW6l, *pW5h, *pW5l;
    cudaGetSymbolAddress(&pH, g_H);
    cudaGetSymbolAddress(&pxh, g_xh);
    cudaGetSymbolAddress(&pxl, g_xl);
    cudaGetSymbolAddress(&pGh, g_Gh);
    cudaGetSymbolAddress(&pGl, g_Gl);
    cudaGetSymbolAddress(&pW6h, g_W6h);
    cudaGetSymbolAddress(&pW6l, g_W6l);
    cudaGetSymbolAddress(&pW5h, g_W5h);
    cudaGetSymbolAddress(&pW5l, g_W5l);

    cudaFuncSetAttribute(k_gemm_t<0>, cudaFuncAttributeMaxDynamicSharedMemorySize, SMEM_BYTES);
    cudaFuncSetAttribute(k_gemm_t<1>, cudaFuncAttributeMaxDynamicSharedMemorySize, SMEM_BYTES);

    dim3 ggrid(NN / BM, FF / BN);

    k_st<<<NN / 8 + 128, 256>>>(x, W3, b3, W6, W5, (bf16*)pxh, (bf16*)pxl);

    // fork: sort chain on side stream, GEMMs on main stream
    cudaStream_t s1 = 0;
    cudaEvent_t e0 = 0, e1 = 0;
    bool forked = false;
    if (cudaStreamCreateWithFlags(&s1, cudaStreamNonBlocking) == cudaSuccess) {
        if (cudaEventCreateWithFlags(&e0, cudaEventDisableTiming) == cudaSuccess &&
            cudaEventCreateWithFlags(&e1, cudaEventDisableTiming) == cudaSuccess) {
            forked = true;
        }
    }

    if (forked) {
        cudaEventRecord(e0, 0);
        cudaStreamWaitEvent(s1, e0, 0);
        k_rankp<<<dim3(NN / 256, RANK_SEGS), 256, 0, s1>>>();
        k_scatter<<<NN / 256, 256, 0, s1>>>();
        k_search<<<NN / 256, 256, 0, s1>>>();
        cudaEventRecord(e1, s1);
    } else {
        k_rankp<<<dim3(NN / 256, RANK_SEGS), 256>>>();
        k_scatter<<<NN / 256, 256>>>();
        k_search<<<NN / 256, 256>>>();
    }

    k_gemm_t<0><<<ggrid, GT, SMEM_BYTES>>>((const bf16*)pxh, (const bf16*)pxl,
                                           (const bf16*)pW6h, (const bf16*)pW6l,
                                           b6, (bf16*)pGh, (bf16*)pGl, nullptr);
    k_gemm_t<1><<<ggrid, GT, SMEM_BYTES>>>((const bf16*)pGh, (const bf16*)pGl,
                                           (const bf16*)pW5h, (const bf16*)pW5l,
                                           nullptr, nullptr, nullptr, (float*)pH);

    if (forked) {
        cudaStreamWaitEvent(0, e1, 0);   // join before csum (needs perm/tsorted/mi)
    }

    k_csum<<<CHUNKS, 256>>>();
    k_scan2<<<FF, CHUNKS>>>();
    k_out<<<NN / 8, 256>>>(x, b5, out);
}

// round 16
// speedup vs baseline: 1.2418x; 1.1499x over previous
#include <cuda_runtime.h>
#include <cuda_bf16.h>
#include <cstdint>

#define NN 8192
#define FF 256
#define CHUNKS 256
#define LCH 32            // NN / CHUNKS
#define RANK_SEGS 4
#define RANK_TILE 2048    // NN / RANK_SEGS
#define QP (NN / 4)       // quarter-point prefix entries (8 per chunk)

#define BM 128
#define BN 128
#define BK 64
#define NSTAGE 3
#define GT 512                                    // GEMM threads (16 warps)
#define ASTR 72                                   // bf16 elems per smem row (64 + 8 pad)
#define STAGE_ELEMS ((BM + 2 * BN) * ASTR)        // 27648 bf16 per stage (Ah,Bh,Bl)
#define SMEM_BYTES (NSTAGE * STAGE_ELEMS * 2)     // 165888 bytes

using bf16 = __nv_bfloat16;

// ---------------- scratch (device globals; no allocations allowed) ----------
__device__ float g_t[NN];
__device__ float g_c[NN];
__device__ float g_diag[NN];
__device__ unsigned g_key[NN];
__device__ int   g_rp[RANK_SEGS * NN];
__device__ float g_tsorted[NN];
__device__ int   g_perm[NN];
__device__ int   g_mi[NN];
__device__ float g_H[NN * FF];                 // H = G @ W5^T
__device__ float g_cs0[CHUNKS * FF];           // chunk sums -> exclusive bases
__device__ float g_cs1[CHUNKS * FF];
__device__ float g_u0[FF];
__device__ float g_u1[FF];
__device__ float g_P0q[QP * FF];               // LOCAL quarter-point partials
__device__ float g_P1q[QP * FF];
// bf16 operands (A sides hi-only; weights hi/lo)
__device__ bf16 g_xh[NN * FF];
__device__ bf16 g_Gh[NN * FF];
__device__ bf16 g_W6h[FF * FF];
__device__ bf16 g_W6l[FF * FF];
__device__ bf16 g_W5h[FF * FF];
__device__ bf16 g_W5l[FF * FF];

__device__ __forceinline__ float leaky_f(float z) { return fmaxf(z, 0.1f * z); }

__device__ __forceinline__ unsigned pack2(float a, float b, unsigned& lo) {
    bf16 ha = __float2bfloat16(a);
    bf16 hb = __float2bfloat16(b);
    bf16 la = __float2bfloat16(a - __bfloat162float(ha));
    bf16 lb = __float2bfloat16(b - __bfloat162float(hb));
    lo = (unsigned)__bfloat16_as_ushort(la) | ((unsigned)__bfloat16_as_ushort(lb) << 16);
    return (unsigned)__bfloat16_as_ushort(ha) | ((unsigned)__bfloat16_as_ushort(hb) << 16);
}

__device__ __forceinline__ unsigned packh(float a, float b) {
    return (unsigned)__bfloat16_as_ushort(__float2bfloat16(a)) |
           ((unsigned)__bfloat16_as_ushort(__float2bfloat16(b)) << 16);
}

// ---------------- kernel 1: s,t,c,diag,keys + x bf16 + W splits --------------
__global__ __launch_bounds__(256) void k_st(const float* __restrict__ x,
                                            const float* __restrict__ W3,
                                            const float* __restrict__ b3,
                                            const float* __restrict__ W6,
                                            const float* __restrict__ W5,
                                            bf16* __restrict__ xh)
{
    int tid = threadIdx.x;
    if (blockIdx.x >= NN / 8) {
        int idx = (blockIdx.x - NN / 8) * 256 + tid;     // 0 .. 2*FF*FF/4-1
        const int half = FF * FF / 4;
        const float* src = (idx < half) ? W6 : W5;
        bf16* dh = (idx < half) ? g_W6h : g_W5h;
        bf16* dl = (idx < half) ? g_W6l : g_W5l;
        int e = (idx < half) ? idx : idx - half;
        float4 v = ((const float4*)src)[e];
        unsigned l0, l1, h0 = pack2(v.x, v.y, l0), h1 = pack2(v.z, v.w, l1);
        ((uint2*)dh)[e] = make_uint2(h0, h1);
        ((uint2*)dl)[e] = make_uint2(l0, l1);
        return;
    }

    __shared__ float w[2 * FF];
    w[tid] = W3[tid];
    w[tid + 256] = W3[tid + 256];
    __syncthreads();

    int warp = tid >> 5;
    int lane = tid & 31;
    int i = blockIdx.x * 8 + warp;
    const float* xr = x + (size_t)i * FF + lane * 8;
    float4 v0 = *(const float4*)xr;
    float4 v1 = *(const float4*)(xr + 4);
    float vv[8] = {v0.x, v0.y, v0.z, v0.w, v1.x, v1.y, v1.z, v1.w};

    float as = 0.f, at = 0.f;
#pragma unroll
    for (int u = 0; u < 8; ++u) {
        as += vv[u] * w[lane * 8 + u];
        at += vv[u] * w[FF + lane * 8 + u];
    }
#pragma unroll
    for (int o = 16; o > 0; o >>= 1) {
        as += __shfl_down_sync(0xFFFFFFFFu, as, o);
        at += __shfl_down_sync(0xFFFFFFFFu, at, o);
    }

    unsigned hp[4];
#pragma unroll
    for (int u = 0; u < 4; ++u) hp[u] = packh(vv[2 * u], vv[2 * u + 1]);
    size_t off = (size_t)i * FF + lane * 8;
    *(uint4*)(xh + off) = make_uint4(hp[0], hp[1], hp[2], hp[3]);

    if (lane == 0) {
        float b = b3[0];
        g_t[i] = at;
        g_c[i] = as + b;
        g_diag[i] = leaky_f(as + at + b);
        unsigned u = __float_as_uint(at);
        u = (u & 0x80000000u) ? ~u : (u | 0x80000000u);
        g_key[i] = (u & 0xFFFFE000u) | (unsigned)i;   // 19-bit value + 13-bit idx
    }
}

// ---------------- counting-sort rank (32-bit keys) ---------------------------
__global__ __launch_bounds__(256) void k_rankp()
{
    __shared__ unsigned tile[RANK_TILE];
    int j = blockIdx.x * 256 + threadIdx.x;
    unsigned kj = g_key[j];
    int base = blockIdx.y * RANK_TILE;
    for (int m = threadIdx.x; m < RANK_TILE; m += 256) tile[m] = g_key[base + m];
    __syncthreads();
    int cnt = 0;
#pragma unroll 32
    for (int m = 0; m < RANK_TILE; ++m) cnt += (tile[m] < kj) ? 1 : 0;
    g_rp[blockIdx.y * NN + j] = cnt;
}

__global__ __launch_bounds__(256) void k_scatter()
{
    int j = blockIdx.x * 256 + threadIdx.x;
    int rank = g_rp[j] + g_rp[NN + j] + g_rp[2 * NN + j] + g_rp[3 * NN + j];
    g_tsorted[rank] = g_t[j];
    g_perm[rank] = j;
}

// ---------------- binary search directly on global ---------------------------
__global__ __launch_bounds__(256) void k_search()
{
    int i = blockIdx.x * 256 + threadIdx.x;
    float keyv = -g_c[i];
    int lo = 0;
#pragma unroll
    for (int step = NN / 2; step > 0; step >>= 1) {
        int nxt = lo + step;
        if (__ldg(&g_tsorted[nxt - 1]) < keyv) lo = nxt;
    }
    g_mi[i] = lo;
}

// ---------------- tensor-core GEMM (2-term: Ah*Bh + Ah*Bl) -------------------
__device__ __forceinline__ void mma16816(float c[4], const unsigned a[4], const unsigned b0, const unsigned b1)
{
    asm volatile(
        "mma.sync.aligned.m16n8k16.row.col.f32.bf16.bf16.f32 "
        "{%0,%1,%2,%3}, {%4,%5,%6,%7}, {%8,%9}, {%0,%1,%2,%3};\n"
        : "+f"(c[0]), "+f"(c[1]), "+f"(c[2]), "+f"(c[3])
        : "r"(a[0]), "r"(a[1]), "r"(a[2]), "r"(a[3]), "r"(b0), "r"(b1));
}

__device__ __forceinline__ void ldsm_x4(unsigned r[4], const bf16* p)
{
    unsigned a = (unsigned)__cvta_generic_to_shared(p);
    asm volatile("ldmatrix.sync.aligned.m8n8.x4.shared.b16 {%0,%1,%2,%3}, [%4];\n"
                 : "=r"(r[0]), "=r"(r[1]), "=r"(r[2]), "=r"(r[3]) : "r"(a));
}

#define CPA(dst, src) asm volatile("cp.async.cg.shared.global [%0], [%1], 16;\n" \
    :: "r"((unsigned)__cvta_generic_to_shared(dst)), "l"(src))

// 512 threads, 16 warps in 4x4 grid; each warp owns 32 rows x 32 cols.
// A is hi-only bf16; B carries hi+lo (weight rounding is the systematically
// amplified error path through the column sums; activation rounding is not).
// MODE 0: C = leaky(acc + bias) -> bf16 (Ch)
// MODE 1: C = acc               -> fp32 (Cf)
template <int MODE>
__global__ __launch_bounds__(GT) void k_gemm_t(
    const bf16* __restrict__ Agh,
    const bf16* __restrict__ Bgh, const bf16* __restrict__ Bgl,
    const float* __restrict__ bias,
    bf16* __restrict__ Ch, float* __restrict__ Cf)
{
    extern __shared__ bf16 sm[];
    const int tid = threadIdx.x;
    const int bm = blockIdx.x * BM;
    const int bn = blockIdx.y * BN;
    const int lane = tid & 31;
    const int warp = tid >> 5;        // 0..15
    const int wm = warp & 3;          // 4 m-tiles of 32
    const int wn = warp >> 2;         // 4 n-tiles of 32
    const int qr = lane >> 2;
    const int qc = (lane & 3) * 2;

    const int aoff = (lane & 15) * ASTR + ((lane >> 4) << 3);
    const int boff = ((lane & 7) + ((lane >> 4) << 3)) * ASTR + (((lane >> 3) & 1) << 3);

    float acc[2][4][4] = {};

    auto load_stage = [&](int kt, int buf) {
        bf16* Ah = sm + buf * STAGE_ELEMS;
        bf16* Bh = Ah + BM * ASTR;
        bf16* Bl = Bh + BN * ASTR;
#pragma unroll
        for (int l = 0; l < 6; ++l) {
            int e = tid + l * GT;              // 0..3071
            int mat = e >> 10;                 // 0=Ah 1=Bh 2=Bl
            int row = (e >> 3) & 127;
            int seg = (e & 7) << 3;            // 0..56 (x8 elems = 16B)
            const bf16* src = (mat == 0) ? Agh : (mat == 1) ? Bgh : Bgl;
            bf16* dst = (mat == 0) ? Ah : (mat == 1) ? Bh : Bl;
            int grow = ((mat == 0) ? bm : bn) + row;
            CPA(dst + row * ASTR + seg, src + (size_t)grow * FF + kt + seg);
        }
        asm volatile("cp.async.commit_group;\n" ::);
    };

    load_stage(0, 0);
    load_stage(BK, 1);

    const int NIT = FF / BK;   // 4
    for (int it = 0; it < NIT; ++it) {
        if (it < NIT - 1) asm volatile("cp.async.wait_group 1;\n" ::);
        else              asm volatile("cp.async.wait_group 0;\n" ::);
        __syncthreads();
        if (it + 2 < NIT) load_stage((it + 2) * BK, (it + 2) % NSTAGE);

        int buf = it % NSTAGE;
        const bf16* Ah = sm + buf * STAGE_ELEMS;
        const bf16* Bh = Ah + BM * ASTR;
        const bf16* Bl = Bh + BN * ASTR;

#pragma unroll
        for (int ks = 0; ks < BK; ks += 16) {
            unsigned ah[2][4];
#pragma unroll
            for (int mi = 0; mi < 2; mi++) {
                int rb = (wm * 32 + mi * 16) * ASTR + ks;
                ldsm_x4(ah[mi], Ah + rb + aoff);
            }
            unsigned bhf[2][4], blf[2][4];
#pragma unroll
            for (int p = 0; p < 2; p++) {
                int nb = (wn * 32 + p * 16) * ASTR + ks;
                ldsm_x4(bhf[p], Bh + nb + boff);
                ldsm_x4(blf[p], Bl + nb + boff);
            }
#pragma unroll
            for (int ni = 0; ni < 4; ni++) {
                unsigned bh0 = bhf[ni >> 1][(ni & 1) * 2], bh1 = bhf[ni >> 1][(ni & 1) * 2 + 1];
                unsigned bl0 = blf[ni >> 1][(ni & 1) * 2], bl1 = blf[ni >> 1][(ni & 1) * 2 + 1];
#pragma unroll
                for (int mi = 0; mi < 2; mi++) {
                    mma16816(acc[mi][ni], ah[mi], bh0, bh1);
                    mma16816(acc[mi][ni], ah[mi], bl0, bl1);
                }
            }
        }
        __syncthreads();
    }

#pragma unroll
    for (int mi = 0; mi < 2; mi++) {
        int r = bm + wm * 32 + mi * 16 + qr;
#pragma unroll
        for (int ni = 0; ni < 4; ni++) {
            int cl = bn + wn * 32 + ni * 8 + qc;
            size_t o0 = (size_t)r * FF + cl;
            size_t o8 = (size_t)(r + 8) * FF + cl;
            if (MODE == 0) {
                float b0 = bias[cl], b1 = bias[cl + 1];
                float v0 = leaky_f(acc[mi][ni][0] + b0);
                float v1 = leaky_f(acc[mi][ni][1] + b1);
                float v2 = leaky_f(acc[mi][ni][2] + b0);
                float v3 = leaky_f(acc[mi][ni][3] + b1);
                *(unsigned*)(Ch + o0) = packh(v0, v1);
                *(unsigned*)(Ch + o8) = packh(v2, v3);
            } else {
                *(float2*)(Cf + o0) = make_float2(acc[mi][ni][0], acc[mi][ni][1]);
                *(float2*)(Cf + o8) = make_float2(acc[mi][ni][2], acc[mi][ni][3]);
            }
        }
    }
}

// ---- chunk sums + LOCAL quarter partials (no scan here) ---------------------
__global__ __launch_bounds__(256) void k_csum()
{
    __shared__ int spj[LCH];
    __shared__ float spt[LCH];
    int c = blockIdx.x;
    int k = threadIdx.x;
    if (k < LCH) {
        spj[k] = g_perm[c * LCH + k];
        spt[k] = g_tsorted[c * LCH + k];
    }
    __syncthreads();
    float a0 = 0.f, a1 = 0.f;
#pragma unroll
    for (int r = 0; r < LCH; ++r) {
        if ((r & 3) == 0) {
            size_t off = (size_t)(c * 8 + (r >> 2)) * FF + k;
            g_P0q[off] = a0;          // local partial before row r of this chunk
            g_P1q[off] = a1;
        }
        float h = g_H[(size_t)spj[r] * FF + k];
        a0 += h;
        a1 += spt[r] * h;
    }
    g_cs0[c * FF + k] = a0;
    g_cs1[c * FF + k] = a1;
}

// ---- parallel scan over chunks: one block per column -------------------------
__global__ __launch_bounds__(CHUNKS) void k_scan2()
{
    __shared__ float s0[CHUNKS], s1[CHUNKS];
    int k = blockIdx.x;            // column 0..FF-1
    int t = threadIdx.x;           // chunk 0..CHUNKS-1
    float v0 = g_cs0[t * FF + k];
    float v1 = g_cs1[t * FF + k];
    float a0 = v0, a1 = v1;
    s0[t] = a0; s1[t] = a1;
    __syncthreads();
#pragma unroll
    for (int d = 1; d < CHUNKS; d <<= 1) {
        float b0 = (t >= d) ? s0[t - d] : 0.f;
        float b1 = (t >= d) ? s1[t - d] : 0.f;
        __syncthreads();
        a0 += b0; a1 += b1;
        s0[t] = a0; s1[t] = a1;
        __syncthreads();
    }
    g_cs0[t * FF + k] = a0 - v0;   // exclusive chunk base
    g_cs1[t * FF + k] = a1 - v1;
    if (t == CHUNKS - 1) { g_u0[k] = a0; g_u1[k] = a1; }
}

// ---------------- output epilogue ---------------------------------------------
__global__ __launch_bounds__(256) void k_out(const float* __restrict__ x,
                                             const float* __restrict__ b5,
                                             float* __restrict__ out)
{
    __shared__ int smi8[8];
    __shared__ float sc8[8], sd8[8];
    int k = threadIdx.x;
    if (k < 8) {
        int i = blockIdx.x * 8 + k;
        smi8[k] = g_mi[i];
        sc8[k] = g_c[i];
        sd8[k] = g_diag[i];
    }
    __syncthreads();
    float u0 = g_u0[k];
    float u1 = g_u1[k];
    float bk = b5[k];
    const float inv = 1.0f / (float)(NN - 1);
#pragma unroll
    for (int r = 0; r < 8; ++r) {
        int i = blockIdx.x * 8 + r;
        int m = smi8[r];
        float ci = sc8[r], di = sd8[r];
        int q = (m + 2) >> 2;          // nearest quarter point
        if (q > QP) q = QP;
        float p0, p1;
        if (q < QP) {
            int c2 = q >> 3;           // owning chunk
            p0 = g_cs0[(size_t)c2 * FF + k] + g_P0q[(size_t)q * FF + k];
            p1 = g_cs1[(size_t)c2 * FF + k] + g_P1q[(size_t)q * FF + k];
        } else {
            p0 = u0;
            p1 = u1;
        }
        int qm = q << 2;
        if (qm <= m) {
            for (int rr = qm; rr < m; ++rr) {
                int j = __ldg(&g_perm[rr]);
                float tv = __ldg(&g_tsorted[rr]);
                float h = g_H[(size_t)j * FF + k];
                p0 += h;
                p1 += tv * h;
            }
        } else {
            for (int rr = m; rr < qm; ++rr) {
                int j = __ldg(&g_perm[rr]);
                float tv = __ldg(&g_tsorted[rr]);
                float h = g_H[(size_t)j * FF + k];
                p0 -= h;
                p1 -= tv * h;
            }
        }
        float h = g_H[(size_t)i * FF + k];
        float val = (ci * u0 + u1 - 0.9f * (ci * p0 + p1) - di * h) * inv;
        out[(size_t)i * FF + k] = leaky_f(val + bk) + x[(size_t)i * FF + k];
    }
}

// ---------------- launch -----------------------------------------------------
extern "C" void kernel_launch(void* const* d_in, const int* in_sizes, int n_in,
                              void* d_out, int out_size)
{
    const float* x  = (const float*)d_in[0];
    const float* W3 = (const float*)d_in[1];
    const float* b3 = (const float*)d_in[2];
    const float* W6 = (const float*)d_in[3];
    const float* b6 = (const float*)d_in[4];
    const float* W5 = (const float*)d_in[5];
    const float* b5 = (const float*)d_in[6];
    float* out = (float*)d_out;

    void *pH, *pxh, *pGh, *pW6h, *pW6l, *pW5h, *pW5l;
    cudaGetSymbolAddress(&pH, g_H);
    cudaGetSymbolAddress(&pxh, g_xh);
    cudaGetSymbolAddress(&pGh, g_Gh);
    cudaGetSymbolAddress(&pW6h, g_W6h);
    cudaGetSymbolAddress(&pW6l, g_W6l);
    cudaGetSymbolAddress(&pW5h, g_W5h);
    cudaGetSymbolAddress(&pW5l, g_W5l);

    cudaFuncSetAttribute(k_gemm_t<0>, cudaFuncAttributeMaxDynamicSharedMemorySize, SMEM_BYTES);
    cudaFuncSetAttribute(k_gemm_t<1>, cudaFuncAttributeMaxDynamicSharedMemorySize, SMEM_BYTES);

    dim3 ggrid(NN / BM, FF / BN);

    k_st<<<NN / 8 + 128, 256>>>(x, W3, b3, W6, W5, (bf16*)pxh);

    // fork: sort chain on side stream, GEMMs on main stream
    cudaStream_t s1 = 0;
    cudaEvent_t e0 = 0, e1 = 0;
    bool forked = false;
    if (cudaStreamCreateWithFlags(&s1, cudaStreamNonBlocking) == cudaSuccess) {
        if (cudaEventCreateWithFlags(&e0, cudaEventDisableTiming) == cudaSuccess &&
            cudaEventCreateWithFlags(&e1, cudaEventDisableTiming) == cudaSuccess) {
            forked = true;
        }
    }

    if (forked) {
        cudaEventRecord(e0, 0);
        cudaStreamWaitEvent(s1, e0, 0);
        k_rankp<<<dim3(NN / 256, RANK_SEGS), 256, 0, s1>>>();
        k_scatter<<<NN / 256, 256, 0, s1>>>();
        k_search<<<NN / 256, 256, 0, s1>>>();
        cudaEventRecord(e1, s1);
    } else {
        k_rankp<<<dim3(NN / 256, RANK_SEGS), 256>>>();
        k_scatter<<<NN / 256, 256>>>();
        k_search<<<NN / 256, 256>>>();
    }

    k_gemm_t<0><<<ggrid, GT, SMEM_BYTES>>>((const bf16*)pxh,
                                           (const bf16*)pW6h, (const bf16*)pW6l,
                                           b6, (bf16*)pGh, nullptr);
    k_gemm_t<1><<<ggrid, GT, SMEM_BYTES>>>((const bf16*)pGh,
                                           (const bf16*)pW5h, (const bf16*)pW5l,
                                           nullptr, nullptr, (float*)pH);

    if (forked) {
        cudaStreamWaitEvent(0, e1, 0);   // join before csum (needs perm/tsorted/mi)
    }

    k_csum<<<CHUNKS, 256>>>();
    k_scan2<<<FF, CHUNKS>>>();
    k_out<<<NN / 8, 256>>>(x, b5, out);
}

// round 17
// speedup vs baseline: 1.2501x; 1.0067x over previous
#include <cuda_runtime.h>
#include <cuda_bf16.h>
#include <cstdint>

#define NN 8192
#define FF 256
#define CHUNKS 256
#define LCH 32            // NN / CHUNKS
#define RANK_SEGS 4
#define RANK_TILE 2048    // NN / RANK_SEGS
#define QP (NN / 4)       // quarter-point prefix entries (8 per chunk)

#define BM 128
#define BN 128
#define BK 64
#define NSTAGE 3
#define GT 512                                    // GEMM threads (16 warps)
#define ASTR 72                                   // bf16 elems per smem row (64 + 8 pad)
#define STAGE_ELEMS ((BM + 2 * BN) * ASTR)        // 27648 bf16 per stage (Ah,Bh,Bl)
#define SMEM_BYTES (NSTAGE * STAGE_ELEMS * 2)     // 165888 bytes

using bf16 = __nv_bfloat16;

// ---------------- scratch (device globals; no allocations allowed) ----------
__device__ float g_t[NN];
__device__ float g_c[NN];
__device__ float g_diag[NN];
__device__ unsigned g_key[NN];
__device__ int   g_rp[RANK_SEGS * NN];
__device__ float g_tsorted[NN];
__device__ int   g_perm[NN];
__device__ int   g_mi[NN];
__device__ bf16  g_Hb[NN * FF];                // H = G @ W5^T   (bf16)
__device__ float g_cs0[CHUNKS * FF];           // chunk sums -> exclusive bases
__device__ float g_cs1[CHUNKS * FF];
__device__ float g_u0[FF];
__device__ float g_u1[FF];
__device__ float g_P0q[QP * FF];               // LOCAL quarter-point partials
__device__ float g_P1q[QP * FF];
// bf16 operands (A sides hi-only; W5 hi/lo, W6 hi-only)
__device__ bf16 g_xh[NN * FF];
__device__ bf16 g_Gh[NN * FF];
__device__ bf16 g_W6h[FF * FF];
__device__ bf16 g_W5h[FF * FF];
__device__ bf16 g_W5l[FF * FF];

__device__ __forceinline__ float leaky_f(float z) { return fmaxf(z, 0.1f * z); }

__device__ __forceinline__ unsigned pack2(float a, float b, unsigned& lo) {
    bf16 ha = __float2bfloat16(a);
    bf16 hb = __float2bfloat16(b);
    bf16 la = __float2bfloat16(a - __bfloat162float(ha));
    bf16 lb = __float2bfloat16(b - __bfloat162float(hb));
    lo = (unsigned)__bfloat16_as_ushort(la) | ((unsigned)__bfloat16_as_ushort(lb) << 16);
    return (unsigned)__bfloat16_as_ushort(ha) | ((unsigned)__bfloat16_as_ushort(hb) << 16);
}

__device__ __forceinline__ unsigned packh(float a, float b) {
    return (unsigned)__bfloat16_as_ushort(__float2bfloat16(a)) |
           ((unsigned)__bfloat16_as_ushort(__float2bfloat16(b)) << 16);
}

// ---------------- kernel 1: s,t,c,diag,keys + x bf16 + W splits --------------
// 1024 row blocks + 64 W-conversion blocks (W6 hi; W5 hi/lo)
__global__ __launch_bounds__(256) void k_st(const float* __restrict__ x,
                                            const float* __restrict__ W3,
                                            const float* __restrict__ b3,
                                            const float* __restrict__ W6,
                                            const float* __restrict__ W5,
                                            bf16* __restrict__ xh)
{
    int tid = threadIdx.x;
    if (blockIdx.x >= NN / 8) {
        int idx = (blockIdx.x - NN / 8) * 256 + tid;     // 0 .. 2*FF*FF/4-1
        const int half = FF * FF / 4;
        if (idx < half) {
            // W6: hi only
            float4 v = ((const float4*)W6)[idx];
            ((uint2*)g_W6h)[idx] = make_uint2(packh(v.x, v.y), packh(v.z, v.w));
        } else {
            // W5: hi + lo
            int e = idx - half;
            float4 v = ((const float4*)W5)[e];
            unsigned l0, l1, h0 = pack2(v.x, v.y, l0), h1 = pack2(v.z, v.w, l1);
            ((uint2*)g_W5h)[e] = make_uint2(h0, h1);
            ((uint2*)g_W5l)[e] = make_uint2(l0, l1);
        }
        return;
    }

    __shared__ float w[2 * FF];
    w[tid] = W3[tid];
    w[tid + 256] = W3[tid + 256];
    __syncthreads();

    int warp = tid >> 5;
    int lane = tid & 31;
    int i = blockIdx.x * 8 + warp;
    const float* xr = x + (size_t)i * FF + lane * 8;
    float4 v0 = *(const float4*)xr;
    float4 v1 = *(const float4*)(xr + 4);
    float vv[8] = {v0.x, v0.y, v0.z, v0.w, v1.x, v1.y, v1.z, v1.w};

    float as = 0.f, at = 0.f;
#pragma unroll
    for (int u = 0; u < 8; ++u) {
        as += vv[u] * w[lane * 8 + u];
        at += vv[u] * w[FF + lane * 8 + u];
    }
#pragma unroll
    for (int o = 16; o > 0; o >>= 1) {
        as += __shfl_down_sync(0xFFFFFFFFu, as, o);
        at += __shfl_down_sync(0xFFFFFFFFu, at, o);
    }

    unsigned hp[4];
#pragma unroll
    for (int u = 0; u < 4; ++u) hp[u] = packh(vv[2 * u], vv[2 * u + 1]);
    size_t off = (size_t)i * FF + lane * 8;
    *(uint4*)(xh + off) = make_uint4(hp[0], hp[1], hp[2], hp[3]);

    if (lane == 0) {
        float b = b3[0];
        g_t[i] = at;
        g_c[i] = as + b;
        g_diag[i] = leaky_f(as + at + b);
        unsigned u = __float_as_uint(at);
        u = (u & 0x80000000u) ? ~u : (u | 0x80000000u);
        g_key[i] = (u & 0xFFFFE000u) | (unsigned)i;   // 19-bit value + 13-bit idx
    }
}

// ---------------- counting-sort rank (32-bit keys) ---------------------------
__global__ __launch_bounds__(256) void k_rankp()
{
    __shared__ unsigned tile[RANK_TILE];
    int j = blockIdx.x * 256 + threadIdx.x;
    unsigned kj = g_key[j];
    int base = blockIdx.y * RANK_TILE;
    for (int m = threadIdx.x; m < RANK_TILE; m += 256) tile[m] = g_key[base + m];
    __syncthreads();
    int cnt = 0;
#pragma unroll 32
    for (int m = 0; m < RANK_TILE; ++m) cnt += (tile[m] < kj) ? 1 : 0;
    g_rp[blockIdx.y * NN + j] = cnt;
}

__global__ __launch_bounds__(256) void k_scatter()
{
    int j = blockIdx.x * 256 + threadIdx.x;
    int rank = g_rp[j] + g_rp[NN + j] + g_rp[2 * NN + j] + g_rp[3 * NN + j];
    g_tsorted[rank] = g_t[j];
    g_perm[rank] = j;
}

// ---------------- binary search directly on global ---------------------------
__global__ __launch_bounds__(256) void k_search()
{
    int i = blockIdx.x * 256 + threadIdx.x;
    float keyv = -g_c[i];
    int lo = 0;
#pragma unroll
    for (int step = NN / 2; step > 0; step >>= 1) {
        int nxt = lo + step;
        if (__ldg(&g_tsorted[nxt - 1]) < keyv) lo = nxt;
    }
    g_mi[i] = lo;
}

// ---------------- tensor-core GEMM (TERMS=1: Ah*Bh; TERMS=2: +Ah*Bl) ---------
__device__ __forceinline__ void mma16816(float c[4], const unsigned a[4], const unsigned b0, const unsigned b1)
{
    asm volatile(
        "mma.sync.aligned.m16n8k16.row.col.f32.bf16.bf16.f32 "
        "{%0,%1,%2,%3}, {%4,%5,%6,%7}, {%8,%9}, {%0,%1,%2,%3};\n"
        : "+f"(c[0]), "+f"(c[1]), "+f"(c[2]), "+f"(c[3])
        : "r"(a[0]), "r"(a[1]), "r"(a[2]), "r"(a[3]), "r"(b0), "r"(b1));
}

__device__ __forceinline__ void ldsm_x4(unsigned r[4], const bf16* p)
{
    unsigned a = (unsigned)__cvta_generic_to_shared(p);
    asm volatile("ldmatrix.sync.aligned.m8n8.x4.shared.b16 {%0,%1,%2,%3}, [%4];\n"
                 : "=r"(r[0]), "=r"(r[1]), "=r"(r[2]), "=r"(r[3]) : "r"(a));
}

#define CPA(dst, src) asm volatile("cp.async.cg.shared.global [%0], [%1], 16;\n" \
    :: "r"((unsigned)__cvta_generic_to_shared(dst)), "l"(src))

// 512 threads, 16 warps in 4x4 grid; each warp owns 32 rows x 32 cols.
// MODE 0: C = leaky(acc + bias) -> bf16 (Ch)
// MODE 1: C = acc               -> bf16 (Ch)
template <int MODE, int TERMS>
__global__ __launch_bounds__(GT) void k_gemm_t(
    const bf16* __restrict__ Agh,
    const bf16* __restrict__ Bgh, const bf16* __restrict__ Bgl,
    const float* __restrict__ bias,
    bf16* __restrict__ Ch)
{
    extern __shared__ bf16 sm[];
    const int tid = threadIdx.x;
    const int bm = blockIdx.x * BM;
    const int bn = blockIdx.y * BN;
    const int lane = tid & 31;
    const int warp = tid >> 5;        // 0..15
    const int wm = warp & 3;          // 4 m-tiles of 32
    const int wn = warp >> 2;         // 4 n-tiles of 32
    const int qr = lane >> 2;
    const int qc = (lane & 3) * 2;

    const int aoff = (lane & 15) * ASTR + ((lane >> 4) << 3);
    const int boff = ((lane & 7) + ((lane >> 4) << 3)) * ASTR + (((lane >> 3) & 1) << 3);

    float acc[2][4][4] = {};

    auto load_stage = [&](int kt, int buf) {
        bf16* Ah = sm + buf * STAGE_ELEMS;
        bf16* Bh = Ah + BM * ASTR;
        bf16* Bl = Bh + BN * ASTR;
        const int NL = (TERMS == 2) ? 6 : 4;     // Ah,Bh[,Bl]
#pragma unroll
        for (int l = 0; l < NL; ++l) {
            int e = tid + l * GT;
            int mat = e >> 10;                 // 0=Ah 1=Bh 2=Bl
            int row = (e >> 3) & 127;
            int seg = (e & 7) << 3;            // 0..56 (x8 elems = 16B)
            const bf16* src = (mat == 0) ? Agh : (mat == 1) ? Bgh : Bgl;
            bf16* dst = (mat == 0) ? Ah : (mat == 1) ? Bh : Bl;
            int grow = ((mat == 0) ? bm : bn) + row;
            CPA(dst + row * ASTR + seg, src + (size_t)grow * FF + kt + seg);
        }
        asm volatile("cp.async.commit_group;\n" ::);
    };

    load_stage(0, 0);
    load_stage(BK, 1);

    const int NIT = FF / BK;   // 4
    for (int it = 0; it < NIT; ++it) {
        if (it < NIT - 1) asm volatile("cp.async.wait_group 1;\n" ::);
        else              asm volatile("cp.async.wait_group 0;\n" ::);
        __syncthreads();
        if (it + 2 < NIT) load_stage((it + 2) * BK, (it + 2) % NSTAGE);

        int buf = it % NSTAGE;
        const bf16* Ah = sm + buf * STAGE_ELEMS;
        const bf16* Bh = Ah + BM * ASTR;
        const bf16* Bl = Bh + BN * ASTR;

#pragma unroll
        for (int ks = 0; ks < BK; ks += 16) {
            unsigned ah[2][4];
#pragma unroll
            for (int mi = 0; mi < 2; mi++) {
                int rb = (wm * 32 + mi * 16) * ASTR + ks;
                ldsm_x4(ah[mi], Ah + rb + aoff);
            }
            unsigned bhf[2][4], blf[2][4];
#pragma unroll
            for (int p = 0; p < 2; p++) {
                int nb = (wn * 32 + p * 16) * ASTR + ks;
                ldsm_x4(bhf[p], Bh + nb + boff);
                if (TERMS == 2) ldsm_x4(blf[p], Bl + nb + boff);
            }
#pragma unroll
            for (int ni = 0; ni < 4; ni++) {
                unsigned bh0 = bhf[ni >> 1][(ni & 1) * 2], bh1 = bhf[ni >> 1][(ni & 1) * 2 + 1];
#pragma unroll
                for (int mi = 0; mi < 2; mi++) {
                    mma16816(acc[mi][ni], ah[mi], bh0, bh1);
                    if (TERMS == 2) {
                        unsigned bl0 = blf[ni >> 1][(ni & 1) * 2], bl1 = blf[ni >> 1][(ni & 1) * 2 + 1];
                        mma16816(acc[mi][ni], ah[mi], bl0, bl1);
                    }
                }
            }
        }
        __syncthreads();
    }

#pragma unroll
    for (int mi = 0; mi < 2; mi++) {
        int r = bm + wm * 32 + mi * 16 + qr;
#pragma unroll
        for (int ni = 0; ni < 4; ni++) {
            int cl = bn + wn * 32 + ni * 8 + qc;
            size_t o0 = (size_t)r * FF + cl;
            size_t o8 = (size_t)(r + 8) * FF + cl;
            if (MODE == 0) {
                float b0 = bias[cl], b1 = bias[cl + 1];
                float v0 = leaky_f(acc[mi][ni][0] + b0);
                float v1 = leaky_f(acc[mi][ni][1] + b1);
                float v2 = leaky_f(acc[mi][ni][2] + b0);
                float v3 = leaky_f(acc[mi][ni][3] + b1);
                *(unsigned*)(Ch + o0) = packh(v0, v1);
                *(unsigned*)(Ch + o8) = packh(v2, v3);
            } else {
                *(unsigned*)(Ch + o0) = packh(acc[mi][ni][0], acc[mi][ni][1]);
                *(unsigned*)(Ch + o8) = packh(acc[mi][ni][2], acc[mi][ni][3]);
            }
        }
    }
}

// ---- chunk sums + LOCAL quarter partials (no scan here) ---------------------
__global__ __launch_bounds__(256) void k_csum()
{
    __shared__ int spj[LCH];
    __shared__ float spt[LCH];
    int c = blockIdx.x;
    int k = threadIdx.x;
    if (k < LCH) {
        spj[k] = g_perm[c * LCH + k];
        spt[k] = g_tsorted[c * LCH + k];
    }
    __syncthreads();
    float a0 = 0.f, a1 = 0.f;
#pragma unroll
    for (int r = 0; r < LCH; ++r) {
        if ((r & 3) == 0) {
            size_t off = (size_t)(c * 8 + (r >> 2)) * FF + k;
            g_P0q[off] = a0;          // local partial before row r of this chunk
            g_P1q[off] = a1;
        }
        float h = __bfloat162float(g_Hb[(size_t)spj[r] * FF + k]);
        a0 += h;
        a1 += spt[r] * h;
    }
    g_cs0[c * FF + k] = a0;
    g_cs1[c * FF + k] = a1;
}

// ---- parallel scan over chunks: one block per column -------------------------
__global__ __launch_bounds__(CHUNKS) void k_scan2()
{
    __shared__ float s0[CHUNKS], s1[CHUNKS];
    int k = blockIdx.x;            // column 0..FF-1
    int t = threadIdx.x;           // chunk 0..CHUNKS-1
    float v0 = g_cs0[t * FF + k];
    float v1 = g_cs1[t * FF + k];
    float a0 = v0, a1 = v1;
    s0[t] = a0; s1[t] = a1;
    __syncthreads();
#pragma unroll
    for (int d = 1; d < CHUNKS; d <<= 1) {
        float b0 = (t >= d) ? s0[t - d] : 0.f;
        float b1 = (t >= d) ? s1[t - d] : 0.f;
        __syncthreads();
        a0 += b0; a1 += b1;
        s0[t] = a0; s1[t] = a1;
        __syncthreads();
    }
    g_cs0[t * FF + k] = a0 - v0;   // exclusive chunk base
    g_cs1[t * FF + k] = a1 - v1;
    if (t == CHUNKS - 1) { g_u0[k] = a0; g_u1[k] = a1; }
}

// ---------------- output epilogue ---------------------------------------------
__global__ __launch_bounds__(256) void k_out(const float* __restrict__ x,
                                             const float* __restrict__ b5,
                                             float* __restrict__ out)
{
    __shared__ int smi8[8];
    __shared__ float sc8[8], sd8[8];
    int k = threadIdx.x;
    if (k < 8) {
        int i = blockIdx.x * 8 + k;
        smi8[k] = g_mi[i];
        sc8[k] = g_c[i];
        sd8[k] = g_diag[i];
    }
    __syncthreads();
    float u0 = g_u0[k];
    float u1 = g_u1[k];
    float bk = b5[k];
    const float inv = 1.0f / (float)(NN - 1);
#pragma unroll
    for (int r = 0; r < 8; ++r) {
        int i = blockIdx.x * 8 + r;
        int m = smi8[r];
        float ci = sc8[r], di = sd8[r];
        int q = (m + 2) >> 2;          // nearest quarter point
        if (q > QP) q = QP;
        float p0, p1;
        if (q < QP) {
            int c2 = q >> 3;           // owning chunk
            p0 = g_cs0[(size_t)c2 * FF + k] + g_P0q[(size_t)q * FF + k];
            p1 = g_cs1[(size_t)c2 * FF + k] + g_P1q[(size_t)q * FF + k];
        } else {
            p0 = u0;
            p1 = u1;
        }
        int qm = q << 2;
        if (qm <= m) {
            for (int rr = qm; rr < m; ++rr) {
                int j = __ldg(&g_perm[rr]);
                float tv = __ldg(&g_tsorted[rr]);
                float h = __bfloat162float(g_Hb[(size_t)j * FF + k]);
                p0 += h;
                p1 += tv * h;
            }
        } else {
            for (int rr = m; rr < qm; ++rr) {
                int j = __ldg(&g_perm[rr]);
                float tv = __ldg(&g_tsorted[rr]);
                float h = __bfloat162float(g_Hb[(size_t)j * FF + k]);
                p0 -= h;
                p1 -= tv * h;
            }
        }
        float h = __bfloat162float(g_Hb[(size_t)i * FF + k]);
        float val = (ci * u0 + u1 - 0.9f * (ci * p0 + p1) - di * h) * inv;
        out[(size_t)i * FF + k] = leaky_f(val + bk) + x[(size_t)i * FF + k];
    }
}

// ---------------- launch -----------------------------------------------------
extern "C" void kernel_launch(void* const* d_in, const int* in_sizes, int n_in,
                              void* d_out, int out_size)
{
    const float* x  = (const float*)d_in[0];
    const float* W3 = (const float*)d_in[1];
    const float* b3 = (const float*)d_in[2];
    const float* W6 = (const float*)d_in[3];
    const float* b6 = (const float*)d_in[4];
    const float* W5 = (const float*)d_in[5];
    const float* b5 = (const float*)d_in[6];
    float* out = (float*)d_out;

    void *pHb, *pxh, *pGh, *pW6h, *pW5h, *pW5l;
    cudaGetSymbolAddress(&pHb, g_Hb);
    cudaGetSymbolAddress(&pxh, g_xh);
    cudaGetSymbolAddress(&pGh, g_Gh);
    cudaGetSymbolAddress(&pW6h, g_W6h);
    cudaGetSymbolAddress(&pW5h, g_W5h);
    cudaGetSymbolAddress(&pW5l, g_W5l);

    cudaFuncSetAttribute((const void*)k_gemm_t<0, 1>, cudaFuncAttributeMaxDynamicSharedMemorySize, SMEM_BYTES);
    cudaFuncSetAttribute((const void*)k_gemm_t<1, 2>, cudaFuncAttributeMaxDynamicSharedMemorySize, SMEM_BYTES);

    dim3 ggrid(NN / BM, FF / BN);

    k_st<<<NN / 8 + 128, 256>>>(x, W3, b3, W6, W5, (bf16*)pxh);

    // fork: sort chain on side stream, GEMMs on main stream
    cudaStream_t s1 = 0;
    cudaEvent_t e0 = 0, e1 = 0;
    bool forked = false;
    if (cudaStreamCreateWithFlags(&s1, cudaStreamNonBlocking) == cudaSuccess) {
        if (cudaEventCreateWithFlags(&e0, cudaEventDisableTiming) == cudaSuccess &&
            cudaEventCreateWithFlags(&e1, cudaEventDisableTiming) == cudaSuccess) {
            forked = true;
        }
    }

    if (forked) {
        cudaEventRecord(e0, 0);
        cudaStreamWaitEvent(s1, e0, 0);
        k_rankp<<<dim3(NN / 256, RANK_SEGS), 256, 0, s1>>>();
        k_scatter<<<NN / 256, 256, 0, s1>>>();
        k_search<<<NN / 256, 256, 0, s1>>>();
        cudaEventRecord(e1, s1);
    } else {
        k_rankp<<<dim3(NN / 256, RANK_SEGS), 256>>>();
        k_scatter<<<NN / 256, 256>>>();
        k_search<<<NN / 256, 256>>>();
    }

    k_gemm_t<0, 1><<<ggrid, GT, SMEM_BYTES>>>((const bf16*)pxh,
                                              (const bf16*)pW6h, nullptr,
                                              b6, (bf16*)pGh);
    k_gemm_t<1, 2><<<ggrid, GT, SMEM_BYTES>>>((const bf16*)pGh,
                                              (const bf16*)pW5h, (const bf16*)pW5l,
                                              nullptr, (bf16*)pHb);

    if (forked) {
        cudaStreamWaitEvent(0, e1, 0);   // join before csum (needs perm/tsorted/mi)
    }

    k_csum<<<CHUNKS, 256>>>();
    k_scan2<<<FF, CHUNKS>>>();
    k_out<<<NN / 8, 256>>>(x, b5, out);
}